// round 15
// baseline (speedup 1.0000x reference)
#include <cuda_runtime.h>
#include <cuda_bf16.h>
#include <cstdint>

#define B_ 8
#define C_ 64
#define H_ 128
#define W_ 128
#define KK_ 9
#define OFFC 18
#define HW_ (H_*W_)

// ---------------------------------------------------------------------------
// helpers
// ---------------------------------------------------------------------------
__device__ __forceinline__ uint32_t smem_u32(const void* p) {
    uint32_t a;
    asm("{ .reg .u64 t; cvta.to.shared.u64 t, %1; cvt.u32.u64 %0, t; }" : "=r"(a) : "l"(p));
    return a;
}
__device__ __forceinline__ void sts128(uint32_t addr, uint4 v) {
    asm volatile("st.shared.v4.b32 [%0], {%1,%2,%3,%4};"
                 :: "r"(addr), "r"(v.x), "r"(v.y), "r"(v.z), "r"(v.w) : "memory");
}
#define LDM4(r, a)                                                              \
    asm volatile("ldmatrix.sync.aligned.m8n8.x4.shared.b16 {%0,%1,%2,%3}, [%4];"\
        : "=r"((r)[0]), "=r"((r)[1]), "=r"((r)[2]), "=r"((r)[3]) : "r"(a))

#define MMA(c, a, b0v, b1v)                                                     \
    asm volatile("mma.sync.aligned.m16n8k16.row.col.f32.bf16.bf16.f32 "         \
        "{%0,%1,%2,%3},{%4,%5,%6,%7},{%8,%9},{%0,%1,%2,%3};"                    \
        : "+f"((c)[0]), "+f"((c)[1]), "+f"((c)[2]), "+f"((c)[3])                \
        : "r"((a)[0]), "r"((a)[1]), "r"((a)[2]), "r"((a)[3]),                   \
          "r"(b0v), "r"(b1v))

// ---------------------------------------------------------------------------
// scratch
// ---------------------------------------------------------------------------
__device__ float g_off[B_ * OFFC * HW_];               // clipped offsets
__device__ __nv_bfloat16 g_wtb[KK_ * 2 * C_ * C_];     // [t][hi/lo][o][c]
__device__ __nv_bfloat16 g_owb[25 * 2 * 32 * C_];      // [tap][hi/lo][oc32pad][c]
__device__ __nv_bfloat16 g_xt_hi[B_ * H_ * W_ * C_];   // x transposed [b][y][px][c]
__device__ __nv_bfloat16 g_xt_lo[B_ * H_ * W_ * C_];

// ---------------------------------------------------------------------------
// Kernel 0a: main-conv weights -> bf16 hi/lo, [t][hi/lo][o][c]
// ---------------------------------------------------------------------------
__global__ void wtb_kernel(const float* __restrict__ w) {
    int i = blockIdx.x * blockDim.x + threadIdx.x;
    if (i >= KK_ * C_ * C_) return;
    int c = i & 63, o = (i >> 6) & 63, t = i >> 12;
    float v = w[(o * C_ + c) * KK_ + t];
    __nv_bfloat16 h = __float2bfloat16(v);
    __nv_bfloat16 l = __float2bfloat16(v - __bfloat162float(h));
    g_wtb[(t * 2 + 0) * 4096 + o * 64 + c] = h;
    g_wtb[(t * 2 + 1) * 4096 + o * 64 + c] = l;
}

// ---------------------------------------------------------------------------
// Kernel 0b: offset-conv weights -> bf16 hi/lo, [tap][s][oc32(zero-pad)][c]
// ---------------------------------------------------------------------------
__global__ void prep_owb(const float* __restrict__ ow) {
    int i = blockIdx.x * blockDim.x + threadIdx.x;
    if (i >= 25 * 2 * 32 * C_) return;
    int c = i & 63, oc = (i >> 6) & 31, s = (i >> 11) & 1, tap = i >> 12;
    float v = (oc < OFFC) ? ow[(oc * C_ + c) * 25 + tap] : 0.f;
    __nv_bfloat16 h = __float2bfloat16(v);
    g_owb[i] = s ? __float2bfloat16(v - __bfloat162float(h)) : h;
}

// ---------------------------------------------------------------------------
// Kernel 0c: transpose x -> [b][y][px][c] bf16 hi/lo (feeds off_mma only)
// ---------------------------------------------------------------------------
__global__ __launch_bounds__(128) void prep_xt(const float* __restrict__ x) {
    const int px = threadIdx.x, y = blockIdx.x, b = blockIdx.y;
    const float* xs = x + (b * C_ * H_ + y) * W_ + px;
    size_t dst = ((size_t)(b * H_ + y) * W_ + px) * C_;
    #pragma unroll
    for (int cg = 0; cg < 8; cg++) {
        __nv_bfloat16 hv[8], lv[8];
        #pragma unroll
        for (int j = 0; j < 8; j++) {
            float v = xs[(cg * 8 + j) * HW_];
            __nv_bfloat16 h = __float2bfloat16(v);
            hv[j] = h;
            lv[j] = __float2bfloat16(v - __bfloat162float(h));
        }
        *(uint4*)(g_xt_hi + dst + cg * 8) = *(const uint4*)hv;
        *(uint4*)(g_xt_lo + dst + cg * 8) = *(const uint4*)lv;
    }
}

// ---------------------------------------------------------------------------
// Kernel 1: offset conv 5x5 pad 2 via mma.sync (R13 version, measured best).
// CTA = 2 output rows, 256 threads / 8 warps, 2-slot A ring, B trimmed to
// 24 oc rows. smem 112640 -> 2 CTAs/SM.
// ---------------------------------------------------------------------------
#define OASL 38016u
#define OBB  76032u
#define OSMEM 112640

__global__ __launch_bounds__(256, 2) void off_mma_kernel(const float* __restrict__ ob) {
    extern __shared__ char sm[];
    const uint32_t sb = smem_u32(sm);
    const int tid = threadIdx.x, l = tid & 31, w = tid >> 5;
    const int y0 = blockIdx.x * 2, b = blockIdx.y;

    float acc[2][3][4];
    #pragma unroll
    for (int mt = 0; mt < 2; mt++)
        #pragma unroll
        for (int nt = 0; nt < 3; nt++)
            #pragma unroll
            for (int r = 0; r < 4; r++) acc[mt][nt][r] = 0.f;

    const int r_out = w >> 2;
    const int pxw   = (w & 3) * 32;

    for (int ky = 0; ky < 5; ky++) {
        __syncthreads();

        int nrows = (ky == 0) ? 2 : 1;
        for (int rr = 0; rr < nrows; rr++) {
            int yy = (ky == 0) ? (y0 - 2 + rr) : (y0 + ky - 1);
            uint32_t slot = sb + (uint32_t)((yy + 8) & 1) * OASL;
            bool inr = (yy >= 0) && (yy < H_);
            const uint4* hs = (const uint4*)(g_xt_hi + (size_t)(b * H_ + (inr ? yy : 0)) * W_ * C_);
            const uint4* ls = (const uint4*)(g_xt_lo + (size_t)(b * H_ + (inr ? yy : 0)) * W_ * C_);
            for (int idx = tid; idx < 2112; idx += 256) {
                int s = idx >= 1056;
                int id = s ? idx - 1056 : idx;
                int row = id >> 3, q = id & 7;
                int px = row - 2;
                uint4 v = make_uint4(0u, 0u, 0u, 0u);
                if (inr && px >= 0 && px < W_) v = (s ? ls : hs)[px * 8 + q];
                sts128(slot + (uint32_t)(s * 19008 + row * 144 + q * 16), v);
            }
        }
        for (int idx = tid; idx < 1920; idx += 256) {
            int kx = idx / 384;
            int rem = idx - kx * 384;
            int s = rem >= 192;
            int id = s ? rem - 192 : rem;
            int oc = id >> 3, q = id & 7;
            uint4 v = ((const uint4*)g_owb)[((ky * 5 + kx) * 2 + s) * 256 + oc * 8 + q];
            sts128(sb + OBB + (uint32_t)(kx * 6912 + s * 3456 + oc * 144 + q * 16), v);
        }
        __syncthreads();

        int yy = y0 + r_out + ky - 2;
        uint32_t aslot = sb + (uint32_t)((yy + 8) & 1) * OASL;
        const uint32_t a_hb = aslot + (uint32_t)((pxw + (l & 15)) * 144 + (l >> 4) * 16);
        const uint32_t a_lb = a_hb + 19008u;
        const uint32_t b_hb = sb + OBB + (uint32_t)((l & 15) * 144 + (l >> 4) * 16);
        const uint32_t b_lb = b_hb + 3456u;

        #pragma unroll
        for (int kx = 0; kx < 5; kx++) {
            #pragma unroll
            for (int cc = 0; cc < 4; cc++) {
                uint32_t ah[2][4], al[2][4], bh[2][4], bl[2][4];
                #pragma unroll
                for (int mt = 0; mt < 2; mt++) {
                    uint32_t ao = (uint32_t)((mt * 16 + kx) * 144 + cc * 32);
                    LDM4(ah[mt], a_hb + ao);
                    LDM4(al[mt], a_lb + ao);
                }
                #pragma unroll
                for (int np = 0; np < 2; np++) {
                    uint32_t bo = (uint32_t)(kx * 6912 + np * 2304 + cc * 32);
                    LDM4(bh[np], b_hb + bo);
                    LDM4(bl[np], b_lb + bo);
                }
                #pragma unroll
                for (int mt = 0; mt < 2; mt++)
                    #pragma unroll
                    for (int nt = 0; nt < 3; nt++) {
                        int np = nt >> 1, h = nt & 1;
                        MMA(acc[mt][nt], ah[mt], bh[np][h], bh[np][h + 2]);
                        MMA(acc[mt][nt], ah[mt], bl[np][h], bl[np][h + 2]);
                        MMA(acc[mt][nt], al[mt], bh[np][h], bh[np][h + 2]);
                    }
            }
        }
    }

    int y = y0 + r_out;
    #pragma unroll
    for (int mt = 0; mt < 2; mt++)
        #pragma unroll
        for (int nt = 0; nt < 3; nt++) {
            int px0 = pxw + mt * 16 + (l >> 2);
            int oc0 = nt * 8 + (l & 3) * 2;
            #pragma unroll
            for (int r = 0; r < 4; r++) {
                int oc = oc0 + (r & 1);
                int px = px0 + (r >> 1) * 8;
                if (oc < OFFC) {
                    float v = acc[mt][nt][r] + ob[oc];
                    v = fminf(fmaxf(v, -1.f), 1.f);
                    g_off[((b * OFFC + oc) * H_ + y) * W_ + px] = v;
                }
            }
        }
}

// ---------------------------------------------------------------------------
// Kernel 2: deformable conv via mma.sync — 4 CTAs/SM (smem 4x55296=216KB,
// regs capped at 128 by launch_bounds). B fragments loaded per np-group to
// cut live registers (8 live B regs instead of 32).
// ---------------------------------------------------------------------------
#define SA_HI 0u
#define SA_LO 18432u
#define SB_HI 36864u
#define SB_LO 46080u
#define DSMEM 55296

__global__ __launch_bounds__(128, 4) void deform_mma_kernel(const float* __restrict__ x,
                                                            float* __restrict__ out) {
    extern __shared__ char sm[];
    const uint32_t sb = smem_u32(sm);
    const int tid = threadIdx.x, l = tid & 31, w = tid >> 5;
    const int y = blockIdx.x, b = blockIdx.y;

    const float* xb   = x + b * C_ * HW_;
    const float* offb = g_off + b * OFFC * HW_;
    const int px  = tid;
    const int pix = y * W_ + px;

    float acc[2][8][4];
    #pragma unroll
    for (int mt = 0; mt < 2; mt++)
        #pragma unroll
        for (int nt = 0; nt < 8; nt++)
            #pragma unroll
            for (int r = 0; r < 4; r++) acc[mt][nt][r] = 0.f;

    for (int t = 0; t < KK_; t++) {
        #pragma unroll
        for (int j = 0; j < 8; j++) {
            int id = tid + j * 128;
            int s   = id >> 9;
            int row = (id >> 3) & 63;
            int cg  = id & 7;
            uint4 v = ((const uint4*)g_wtb)[(t * 2 + s) * 512 + row * 8 + cg];
            sts128(sb + (s ? SB_LO : SB_HI) + (uint32_t)(row * 144 + cg * 16), v);
        }

        float dy = offb[(2 * t)     * HW_ + pix];
        float dx = offb[(2 * t + 1) * HW_ + pix];
        int ti = t / 3, tj = t % 3;
        float py  = (float)y  + (float)(ti - 1) + dy;
        float pxf = (float)px + (float)(tj - 1) + dx;

        float y0f = floorf(py), x0f = floorf(pxf);
        float fy = py - y0f, fx = pxf - x0f;
        int y0 = (int)y0f, x0 = (int)x0f, y1 = y0 + 1, x1 = x0 + 1;

        bool vy0 = (y0 >= 0) && (y0 < H_);
        bool vy1 = (y1 >= 0) && (y1 < H_);
        bool vx0 = (x0 >= 0) && (x0 < W_);
        bool vx1 = (x1 >= 0) && (x1 < W_);

        float w00 = (1.f - fy) * (1.f - fx) * (float)(vy0 && vx0);
        float w01 = (1.f - fy) * fx         * (float)(vy0 && vx1);
        float w10 = fy * (1.f - fx)         * (float)(vy1 && vx0);
        float w11 = fy * fx                 * (float)(vy1 && vx1);

        int cy0 = min(max(y0, 0), H_ - 1), cy1 = min(max(y1, 0), H_ - 1);
        int cx0 = min(max(x0, 0), W_ - 1), cx1 = min(max(x1, 0), W_ - 1);
        int i00 = cy0 * W_ + cx0, i01 = cy0 * W_ + cx1;
        int i10 = cy1 * W_ + cx0, i11 = cy1 * W_ + cx1;

        #pragma unroll
        for (int cg = 0; cg < 8; cg++) {
            __nv_bfloat16 hv[8], lv[8];
            #pragma unroll
            for (int j = 0; j < 8; j++) {
                const float* xc = xb + (cg * 8 + j) * HW_;
                float s = w00 * xc[i00] + w01 * xc[i01]
                        + w10 * xc[i10] + w11 * xc[i11];
                __nv_bfloat16 h = __float2bfloat16(s);
                hv[j] = h;
                lv[j] = __float2bfloat16(s - __bfloat162float(h));
            }
            uint32_t off = (uint32_t)(px * 144 + cg * 16);
            sts128(sb + SA_HI + off, *(const uint4*)hv);
            sts128(sb + SA_LO + off, *(const uint4*)lv);
        }

        __syncthreads();

        uint32_t a_h = sb + SA_HI + (uint32_t)((w * 32 + (l & 15)) * 144 + (l >> 4) * 16);
        uint32_t a_l = a_h + (SA_LO - SA_HI);
        uint32_t b_h = sb + SB_HI + (uint32_t)((l & 15) * 144 + (l >> 4) * 16);
        uint32_t b_l = b_h + (SB_LO - SB_HI);

        #pragma unroll
        for (int k = 0; k < 4; k++) {
            uint32_t ah[2][4], al[2][4];
            #pragma unroll
            for (int mt = 0; mt < 2; mt++) {
                LDM4(ah[mt], a_h + mt * (16 * 144) + k * 32);
                LDM4(al[mt], a_l + mt * (16 * 144) + k * 32);
            }
            #pragma unroll
            for (int np = 0; np < 4; np++) {
                uint32_t bh[4], bl[4];
                LDM4(bh, b_h + np * (16 * 144) + k * 32);
                LDM4(bl, b_l + np * (16 * 144) + k * 32);
                #pragma unroll
                for (int mt = 0; mt < 2; mt++)
                    #pragma unroll
                    for (int h = 0; h < 2; h++) {
                        int nt = np * 2 + h;
                        MMA(acc[mt][nt], ah[mt], bh[h], bh[h + 2]);
                        MMA(acc[mt][nt], ah[mt], bl[h], bl[h + 2]);
                        MMA(acc[mt][nt], al[mt], bh[h], bh[h + 2]);
                    }
            }
        }
        __syncthreads();
    }

    #pragma unroll
    for (int mt = 0; mt < 2; mt++)
        #pragma unroll
        for (int nt = 0; nt < 8; nt++) {
            int row = w * 32 + mt * 16 + (l >> 2);
            int o   = nt * 8 + (l & 3) * 2;
            float* p = out + b * C_ * HW_ + o * HW_ + y * W_ + row;
            p[0]       = acc[mt][nt][0];
            p[HW_]     = acc[mt][nt][1];
            p[8]       = acc[mt][nt][2];
            p[HW_ + 8] = acc[mt][nt][3];
        }
}

// ---------------------------------------------------------------------------
extern "C" void kernel_launch(void* const* d_in, const int* in_sizes, int n_in,
                              void* d_out, int out_size) {
    const float* x    = (const float*)d_in[0];   // [8,64,128,128]
    const float* w    = (const float*)d_in[1];   // [64,64,3,3]
    const float* ow   = (const float*)d_in[2];   // [18,64,5,5]
    const float* obia = (const float*)d_in[3];   // [18]
    float* out = (float*)d_out;

    cudaFuncSetAttribute(off_mma_kernel,
                         cudaFuncAttributeMaxDynamicSharedMemorySize, OSMEM);
    cudaFuncSetAttribute(deform_mma_kernel,
                         cudaFuncAttributeMaxDynamicSharedMemorySize, DSMEM);

    wtb_kernel<<<(KK_ * C_ * C_ + 255) / 256, 256>>>(w);
    prep_owb<<<(25 * 2 * 32 * C_ + 255) / 256, 256>>>(ow);

    dim3 gx(H_, B_);
    prep_xt<<<gx, 128>>>(x);

    dim3 g1(H_ / 2, B_);
    off_mma_kernel<<<g1, 256, OSMEM>>>(obia);

    dim3 g2(H_, B_);
    deform_mma_kernel<<<g2, 128, DSMEM>>>(x, out);
}

// round 17
// speedup vs baseline: 1.0808x; 1.0808x over previous
#include <cuda_runtime.h>
#include <cuda_bf16.h>
#include <cstdint>

#define B_ 8
#define C_ 64
#define H_ 128
#define W_ 128
#define KK_ 9
#define OFFC 18
#define HW_ (H_*W_)

// ---------------------------------------------------------------------------
// helpers
// ---------------------------------------------------------------------------
__device__ __forceinline__ uint32_t smem_u32(const void* p) {
    uint32_t a;
    asm("{ .reg .u64 t; cvta.to.shared.u64 t, %1; cvt.u32.u64 %0, t; }" : "=r"(a) : "l"(p));
    return a;
}
__device__ __forceinline__ void sts128(uint32_t addr, uint4 v) {
    asm volatile("st.shared.v4.b32 [%0], {%1,%2,%3,%4};"
                 :: "r"(addr), "r"(v.x), "r"(v.y), "r"(v.z), "r"(v.w) : "memory");
}
#define LDM4(r, a)                                                              \
    asm volatile("ldmatrix.sync.aligned.m8n8.x4.shared.b16 {%0,%1,%2,%3}, [%4];"\
        : "=r"((r)[0]), "=r"((r)[1]), "=r"((r)[2]), "=r"((r)[3]) : "r"(a))

#define MMA(c, a, b0v, b1v)                                                     \
    asm volatile("mma.sync.aligned.m16n8k16.row.col.f32.bf16.bf16.f32 "         \
        "{%0,%1,%2,%3},{%4,%5,%6,%7},{%8,%9},{%0,%1,%2,%3};"                    \
        : "+f"((c)[0]), "+f"((c)[1]), "+f"((c)[2]), "+f"((c)[3])                \
        : "r"((a)[0]), "r"((a)[1]), "r"((a)[2]), "r"((a)[3]),                   \
          "r"(b0v), "r"(b1v))

// ---------------------------------------------------------------------------
// scratch
// ---------------------------------------------------------------------------
__device__ float g_off[B_ * OFFC * HW_];               // clipped offsets
__device__ __nv_bfloat16 g_wtb[KK_ * 2 * C_ * C_];     // [t][hi/lo][o][c]
__device__ __nv_bfloat16 g_owb[25 * 2 * 32 * C_];      // [tap][hi/lo][oc32pad][c]
__device__ __nv_bfloat16 g_xt_hi[B_ * H_ * W_ * C_];   // x transposed [b][y][px][c]
__device__ __nv_bfloat16 g_xt_lo[B_ * H_ * W_ * C_];

// ---------------------------------------------------------------------------
// Kernel 0a: fused weight prep (main-conv split + offset-conv split)
// ---------------------------------------------------------------------------
__global__ void prep_w(const float* __restrict__ w, const float* __restrict__ ow) {
    int i = blockIdx.x * blockDim.x + threadIdx.x;
    if (i < KK_ * C_ * C_) {
        int c = i & 63, o = (i >> 6) & 63, t = i >> 12;
        float v = w[(o * C_ + c) * KK_ + t];
        __nv_bfloat16 h = __float2bfloat16(v);
        __nv_bfloat16 l = __float2bfloat16(v - __bfloat162float(h));
        g_wtb[(t * 2 + 0) * 4096 + o * 64 + c] = h;
        g_wtb[(t * 2 + 1) * 4096 + o * 64 + c] = l;
        return;
    }
    int j = i - KK_ * C_ * C_;
    if (j >= 25 * 2 * 32 * C_) return;
    int c = j & 63, oc = (j >> 6) & 31, s = (j >> 11) & 1, tap = j >> 12;
    float v = (oc < OFFC) ? ow[(oc * C_ + c) * 25 + tap] : 0.f;
    __nv_bfloat16 h = __float2bfloat16(v);
    g_owb[j] = s ? __float2bfloat16(v - __bfloat162float(h)) : h;
}

// ---------------------------------------------------------------------------
// Kernel 0c: transpose x -> [b][y][px][c] bf16 hi/lo (feeds off_mma only)
// ---------------------------------------------------------------------------
__global__ __launch_bounds__(128) void prep_xt(const float* __restrict__ x) {
    const int px = threadIdx.x, y = blockIdx.x, b = blockIdx.y;
    const float* xs = x + (b * C_ * H_ + y) * W_ + px;
    size_t dst = ((size_t)(b * H_ + y) * W_ + px) * C_;
    #pragma unroll
    for (int cg = 0; cg < 8; cg++) {
        __nv_bfloat16 hv[8], lv[8];
        #pragma unroll
        for (int j = 0; j < 8; j++) {
            float v = xs[(cg * 8 + j) * HW_];
            __nv_bfloat16 h = __float2bfloat16(v);
            hv[j] = h;
            lv[j] = __float2bfloat16(v - __bfloat162float(h));
        }
        *(uint4*)(g_xt_hi + dst + cg * 8) = *(const uint4*)hv;
        *(uint4*)(g_xt_lo + dst + cg * 8) = *(const uint4*)lv;
    }
}

// ---------------------------------------------------------------------------
// Kernel 1: offset conv 5x5 pad 2 via mma.sync (exact R13 — measured best).
// ---------------------------------------------------------------------------
#define OASL 38016u
#define OBB  76032u
#define OSMEM 112640

__global__ __launch_bounds__(256, 2) void off_mma_kernel(const float* __restrict__ ob) {
    extern __shared__ char sm[];
    const uint32_t sb = smem_u32(sm);
    const int tid = threadIdx.x, l = tid & 31, w = tid >> 5;
    const int y0 = blockIdx.x * 2, b = blockIdx.y;

    float acc[2][3][4];
    #pragma unroll
    for (int mt = 0; mt < 2; mt++)
        #pragma unroll
        for (int nt = 0; nt < 3; nt++)
            #pragma unroll
            for (int r = 0; r < 4; r++) acc[mt][nt][r] = 0.f;

    const int r_out = w >> 2;
    const int pxw   = (w & 3) * 32;

    for (int ky = 0; ky < 5; ky++) {
        __syncthreads();

        int nrows = (ky == 0) ? 2 : 1;
        for (int rr = 0; rr < nrows; rr++) {
            int yy = (ky == 0) ? (y0 - 2 + rr) : (y0 + ky - 1);
            uint32_t slot = sb + (uint32_t)((yy + 8) & 1) * OASL;
            bool inr = (yy >= 0) && (yy < H_);
            const uint4* hs = (const uint4*)(g_xt_hi + (size_t)(b * H_ + (inr ? yy : 0)) * W_ * C_);
            const uint4* ls = (const uint4*)(g_xt_lo + (size_t)(b * H_ + (inr ? yy : 0)) * W_ * C_);
            for (int idx = tid; idx < 2112; idx += 256) {
                int s = idx >= 1056;
                int id = s ? idx - 1056 : idx;
                int row = id >> 3, q = id & 7;
                int px = row - 2;
                uint4 v = make_uint4(0u, 0u, 0u, 0u);
                if (inr && px >= 0 && px < W_) v = (s ? ls : hs)[px * 8 + q];
                sts128(slot + (uint32_t)(s * 19008 + row * 144 + q * 16), v);
            }
        }
        for (int idx = tid; idx < 1920; idx += 256) {
            int kx = idx / 384;
            int rem = idx - kx * 384;
            int s = rem >= 192;
            int id = s ? rem - 192 : rem;
            int oc = id >> 3, q = id & 7;
            uint4 v = ((const uint4*)g_owb)[((ky * 5 + kx) * 2 + s) * 256 + oc * 8 + q];
            sts128(sb + OBB + (uint32_t)(kx * 6912 + s * 3456 + oc * 144 + q * 16), v);
        }
        __syncthreads();

        int yy = y0 + r_out + ky - 2;
        uint32_t aslot = sb + (uint32_t)((yy + 8) & 1) * OASL;
        const uint32_t a_hb = aslot + (uint32_t)((pxw + (l & 15)) * 144 + (l >> 4) * 16);
        const uint32_t a_lb = a_hb + 19008u;
        const uint32_t b_hb = sb + OBB + (uint32_t)((l & 15) * 144 + (l >> 4) * 16);
        const uint32_t b_lb = b_hb + 3456u;

        #pragma unroll
        for (int kx = 0; kx < 5; kx++) {
            #pragma unroll
            for (int cc = 0; cc < 4; cc++) {
                uint32_t ah[2][4], al[2][4], bh[2][4], bl[2][4];
                #pragma unroll
                for (int mt = 0; mt < 2; mt++) {
                    uint32_t ao = (uint32_t)((mt * 16 + kx) * 144 + cc * 32);
                    LDM4(ah[mt], a_hb + ao);
                    LDM4(al[mt], a_lb + ao);
                }
                #pragma unroll
                for (int np = 0; np < 2; np++) {
                    uint32_t bo = (uint32_t)(kx * 6912 + np * 2304 + cc * 32);
                    LDM4(bh[np], b_hb + bo);
                    LDM4(bl[np], b_lb + bo);
                }
                #pragma unroll
                for (int mt = 0; mt < 2; mt++)
                    #pragma unroll
                    for (int nt = 0; nt < 3; nt++) {
                        int np = nt >> 1, h = nt & 1;
                        MMA(acc[mt][nt], ah[mt], bh[np][h], bh[np][h + 2]);
                        MMA(acc[mt][nt], ah[mt], bl[np][h], bl[np][h + 2]);
                        MMA(acc[mt][nt], al[mt], bh[np][h], bh[np][h + 2]);
                    }
            }
        }
    }

    int y = y0 + r_out;
    #pragma unroll
    for (int mt = 0; mt < 2; mt++)
        #pragma unroll
        for (int nt = 0; nt < 3; nt++) {
            int px0 = pxw + mt * 16 + (l >> 2);
            int oc0 = nt * 8 + (l & 3) * 2;
            #pragma unroll
            for (int r = 0; r < 4; r++) {
                int oc = oc0 + (r & 1);
                int px = px0 + (r >> 1) * 8;
                if (oc < OFFC) {
                    float v = acc[mt][nt][r] + ob[oc];
                    v = fminf(fmaxf(v, -1.f), 1.f);
                    g_off[((b * OFFC + oc) * H_ + y) * W_ + px] = v;
                }
            }
        }
}

// ---------------------------------------------------------------------------
// Kernel 2: deformable conv via mma.sync — R13 structure ((128,3), full
// B-fragment preload) + smem-staged coalesced epilogue.
// ---------------------------------------------------------------------------
#define SA_HI 0u
#define SA_LO 18432u
#define SB_HI 36864u
#define SB_LO 46080u
#define DSMEM 55296

__global__ __launch_bounds__(128, 3) void deform_mma_kernel(const float* __restrict__ x,
                                                            float* __restrict__ out) {
    extern __shared__ char sm[];
    const uint32_t sb = smem_u32(sm);
    const int tid = threadIdx.x, l = tid & 31, w = tid >> 5;
    const int y = blockIdx.x, b = blockIdx.y;

    const float* xb   = x + b * C_ * HW_;
    const float* offb = g_off + b * OFFC * HW_;
    const int px  = tid;
    const int pix = y * W_ + px;

    float acc[2][8][4];
    #pragma unroll
    for (int mt = 0; mt < 2; mt++)
        #pragma unroll
        for (int nt = 0; nt < 8; nt++)
            #pragma unroll
            for (int r = 0; r < 4; r++) acc[mt][nt][r] = 0.f;

    for (int t = 0; t < KK_; t++) {
        #pragma unroll
        for (int j = 0; j < 8; j++) {
            int id = tid + j * 128;
            int s   = id >> 9;
            int row = (id >> 3) & 63;
            int cg  = id & 7;
            uint4 v = ((const uint4*)g_wtb)[(t * 2 + s) * 512 + row * 8 + cg];
            sts128(sb + (s ? SB_LO : SB_HI) + (uint32_t)(row * 144 + cg * 16), v);
        }

        float dy = offb[(2 * t)     * HW_ + pix];
        float dx = offb[(2 * t + 1) * HW_ + pix];
        int ti = t / 3, tj = t % 3;
        float py  = (float)y  + (float)(ti - 1) + dy;
        float pxf = (float)px + (float)(tj - 1) + dx;

        float y0f = floorf(py), x0f = floorf(pxf);
        float fy = py - y0f, fx = pxf - x0f;
        int y0 = (int)y0f, x0 = (int)x0f, y1 = y0 + 1, x1 = x0 + 1;

        bool vy0 = (y0 >= 0) && (y0 < H_);
        bool vy1 = (y1 >= 0) && (y1 < H_);
        bool vx0 = (x0 >= 0) && (x0 < W_);
        bool vx1 = (x1 >= 0) && (x1 < W_);

        float w00 = (1.f - fy) * (1.f - fx) * (float)(vy0 && vx0);
        float w01 = (1.f - fy) * fx         * (float)(vy0 && vx1);
        float w10 = fy * (1.f - fx)         * (float)(vy1 && vx0);
        float w11 = fy * fx                 * (float)(vy1 && vx1);

        int cy0 = min(max(y0, 0), H_ - 1), cy1 = min(max(y1, 0), H_ - 1);
        int cx0 = min(max(x0, 0), W_ - 1), cx1 = min(max(x1, 0), W_ - 1);
        int i00 = cy0 * W_ + cx0, i01 = cy0 * W_ + cx1;
        int i10 = cy1 * W_ + cx0, i11 = cy1 * W_ + cx1;

        #pragma unroll
        for (int cg = 0; cg < 8; cg++) {
            __nv_bfloat16 hv[8], lv[8];
            #pragma unroll
            for (int j = 0; j < 8; j++) {
                const float* xc = xb + (cg * 8 + j) * HW_;
                float s = w00 * xc[i00] + w01 * xc[i01]
                        + w10 * xc[i10] + w11 * xc[i11];
                __nv_bfloat16 h = __float2bfloat16(s);
                hv[j] = h;
                lv[j] = __float2bfloat16(s - __bfloat162float(h));
            }
            uint32_t off = (uint32_t)(px * 144 + cg * 16);
            sts128(sb + SA_HI + off, *(const uint4*)hv);
            sts128(sb + SA_LO + off, *(const uint4*)lv);
        }

        __syncthreads();

        uint32_t a_h = sb + SA_HI + (uint32_t)((w * 32 + (l & 15)) * 144 + (l >> 4) * 16);
        uint32_t a_l = a_h + (SA_LO - SA_HI);
        uint32_t b_h = sb + SB_HI + (uint32_t)((l & 15) * 144 + (l >> 4) * 16);
        uint32_t b_l = b_h + (SB_LO - SB_HI);

        #pragma unroll
        for (int k = 0; k < 4; k++) {
            uint32_t ah[2][4], al[2][4], bh[4][4], bl[4][4];
            #pragma unroll
            for (int mt = 0; mt < 2; mt++) {
                LDM4(ah[mt], a_h + mt * (16 * 144) + k * 32);
                LDM4(al[mt], a_l + mt * (16 * 144) + k * 32);
            }
            #pragma unroll
            for (int np = 0; np < 4; np++) {
                LDM4(bh[np], b_h + np * (16 * 144) + k * 32);
                LDM4(bl[np], b_l + np * (16 * 144) + k * 32);
            }
            #pragma unroll
            for (int mt = 0; mt < 2; mt++)
                #pragma unroll
                for (int nt = 0; nt < 8; nt++) {
                    int np = nt >> 1, h = nt & 1;
                    MMA(acc[mt][nt], ah[mt], bh[np][h], bh[np][h + 2]);
                    MMA(acc[mt][nt], ah[mt], bl[np][h], bl[np][h + 2]);
                    MMA(acc[mt][nt], al[mt], bh[np][h], bh[np][h + 2]);
                }
        }
        __syncthreads();
    }

    // ---- epilogue: stage through smem [row][65] f32, then coalesced STG ----
    float* so = (float*)sm;   // 128*65*4 = 33280 B, buffers dead after barrier
    #pragma unroll
    for (int mt = 0; mt < 2; mt++)
        #pragma unroll
        for (int nt = 0; nt < 8; nt++) {
            int row = w * 32 + mt * 16 + (l >> 2);
            int o   = nt * 8 + (l & 3) * 2;
            so[row * 65 + o]           = acc[mt][nt][0];
            so[row * 65 + o + 1]       = acc[mt][nt][1];
            so[(row + 8) * 65 + o]     = acc[mt][nt][2];
            so[(row + 8) * 65 + o + 1] = acc[mt][nt][3];
        }
    __syncthreads();

    float* ob = out + b * C_ * HW_ + y * W_ + tid;
    #pragma unroll
    for (int o = 0; o < C_; o++)
        ob[o * HW_] = so[tid * 65 + o];
}

// ---------------------------------------------------------------------------
extern "C" void kernel_launch(void* const* d_in, const int* in_sizes, int n_in,
                              void* d_out, int out_size) {
    const float* x    = (const float*)d_in[0];   // [8,64,128,128]
    const float* w    = (const float*)d_in[1];   // [64,64,3,3]
    const float* ow   = (const float*)d_in[2];   // [18,64,5,5]
    const float* obia = (const float*)d_in[3];   // [18]
    float* out = (float*)d_out;

    cudaFuncSetAttribute(off_mma_kernel,
                         cudaFuncAttributeMaxDynamicSharedMemorySize, OSMEM);
    cudaFuncSetAttribute(deform_mma_kernel,
                         cudaFuncAttributeMaxDynamicSharedMemorySize, DSMEM);

    int prep_total = KK_ * C_ * C_ + 25 * 2 * 32 * C_;
    prep_w<<<(prep_total + 255) / 256, 256>>>(w, ow);

    dim3 gx(H_, B_);
    prep_xt<<<gx, 128>>>(x);

    dim3 g1(H_ / 2, B_);
    off_mma_kernel<<<g1, 256, OSMEM>>>(obia);

    dim3 g2(H_, B_);
    deform_mma_kernel<<<g2, 128, DSMEM>>>(x, out);
}